// round 2
// baseline (speedup 1.0000x reference)
#include <cuda_runtime.h>

// out[b, r, c] = x[b, r, c] * weight[c], N = 4096 (power of two)
// Pure HBM-streaming elementwise: float4 vectorized, exact grid cover.

__global__ void __launch_bounds__(256) scale_lastdim_kernel(
    const float4* __restrict__ x4,
    const float*  __restrict__ w,
    float4* __restrict__ out4,
    long long n4)  // number of float4 elements
{
    long long i = (long long)blockIdx.x * blockDim.x + threadIdx.x;
    if (i >= n4) return;

    // column of first scalar in this float4: (i*4) mod 4096
    int col = (int)((i << 2) & 4095LL);

    float4 xv = x4[i];
    // weight is 16 KB — L1-resident after first wave; read via read-only path
    const float4 wv = __ldg((const float4*)(w + col));

    float4 ov;
    ov.x = xv.x * wv.x;
    ov.y = xv.y * wv.y;
    ov.z = xv.z * wv.z;
    ov.w = xv.w * wv.w;
    out4[i] = ov;
}

extern "C" void kernel_launch(void* const* d_in, const int* in_sizes, int n_in,
                              void* d_out, int out_size)
{
    const float* x = (const float*)d_in[0];
    const float* w = (const float*)d_in[1];
    float* out = (float*)d_out;

    long long n = (long long)out_size;   // 4*4096*4096 = 67108864
    long long n4 = n >> 2;               // 16777216 float4s

    const int threads = 256;
    long long blocks = (n4 + threads - 1) / threads;  // 65536

    scale_lastdim_kernel<<<(unsigned)blocks, threads>>>(
        (const float4*)x, w, (float4*)out, n4);
}

// round 3
// speedup vs baseline: 1.0062x; 1.0062x over previous
#include <cuda_runtime.h>

// out[b, r, c] = x[b, r, c] * weight[c], N = 4096 (power of two)
// Pure HBM stream. 4x float4 per thread, front-batched loads (MLP=4 per thread),
// streaming cache hints on x/out (no reuse), exact grid cover.

#define UNROLL 4

__global__ void __launch_bounds__(256) scale_lastdim_u4_kernel(
    const float4* __restrict__ x4,
    const float*  __restrict__ w,
    float4* __restrict__ out4)
{
    // Each block covers a contiguous chunk of 256*UNROLL float4s (64 KB in / 64 KB out)
    long long base = (long long)blockIdx.x * (256 * UNROLL) + threadIdx.x;

    // Front-batch all loads: 4 independent LDG.128 in flight per thread
    float4 xv[UNROLL];
#pragma unroll
    for (int k = 0; k < UNROLL; k++)
        xv[k] = __ldcs(&x4[base + (long long)k * 256]);

#pragma unroll
    for (int k = 0; k < UNROLL; k++) {
        long long i = base + (long long)k * 256;
        int col = (int)((i << 2) & 4095LL);          // (i*4) mod 4096
        const float4 wv = __ldg((const float4*)(w + col));  // 16 KB, L1-resident

        float4 ov;
        ov.x = xv[k].x * wv.x;
        ov.y = xv[k].y * wv.y;
        ov.z = xv[k].z * wv.z;
        ov.w = xv[k].w * wv.w;
        __stcs(&out4[i], ov);
    }
}

extern "C" void kernel_launch(void* const* d_in, const int* in_sizes, int n_in,
                              void* d_out, int out_size)
{
    const float* x = (const float*)d_in[0];
    const float* w = (const float*)d_in[1];
    float* out = (float*)d_out;

    long long n  = (long long)out_size;  // 4*4096*4096 = 67108864
    long long n4 = n >> 2;               // 16777216 float4s

    const int threads = 256;
    long long blocks = n4 / (threads * UNROLL);   // 16384, exact cover

    scale_lastdim_u4_kernel<<<(unsigned)blocks, threads>>>(
        (const float4*)x, w, (float4*)out);
}